// round 6
// baseline (speedup 1.0000x reference)
#include <cuda_runtime.h>
#include <cstdint>

// ============================================================================
// QuantizedYOLOv3Tiny — round 6: sparse ternary convs, no >48KB smem
// Ternary weights are 88-97.6% zero. Prep builds per-cout compacted entry
// lists {tile_offset, weight_word}; convs iterate only nonzero words
// (warp-uniform). Exact math. conv1 = s * sum(+/- x) FADD gathers.
// L7/L10 (26 planes) run two-phase (13 planes per phase, 25KB static smem).
// ============================================================================

#define ALIGN16 __align__(16)

__device__ float g_scale[10];

// sparse entries: {off, weight_word}; per-layer constants (entry units):
//  idx L=1..9 (net layers 2..10)
//  MAXE: 18,18,36,72,126,234,52,126,234
//  EB:    0,144,432,1584,5616,18720,67392,70304,83408   total 90428
//  CB:    0,  8, 24,  56,  112,  216,  424,  480,  584  total 614
__device__ ALIGN16 int2 g_entries[90428];
__device__ int g_cnt[614];
__device__ unsigned short g_c1p[8 * 32], g_c1m[8 * 32];
__device__ int g_c1cnt[16];

// planar activation buffers: word = 4 channels of one pixel, [n][k][H*W]
__device__ ALIGN16 uint32_t g_act1[16*2*320*320];
__device__ ALIGN16 uint32_t g_act2[16*2*160*160];
__device__ ALIGN16 uint32_t g_act3[16*4*80*80];
__device__ ALIGN16 uint32_t g_act4[16*8*40*40];
__device__ ALIGN16 uint32_t g_act5[16*14*20*20];
__device__ ALIGN16 uint32_t g_act6[16*26*20*20];
__device__ ALIGN16 uint32_t g_act7[16*52*20*20];
__device__ ALIGN16 uint32_t g_act8[16*14*20*20];
__device__ ALIGN16 uint32_t g_act9[16*26*20*20];

// ----------------------------------------------------------------------------
// absmax for 5 layers starting at `base` (two launches so conv1 is launch #4,
// landing in the ncu capture slot)
// ----------------------------------------------------------------------------
__global__ void absmax5(const float* w0, const float* w1, const float* w2,
                        const float* w3, const float* w4, const float* w5,
                        const float* w6, const float* w7, const float* w8,
                        const float* w9, int base) {
    const float* ws[10] = {w0,w1,w2,w3,w4,w5,w6,w7,w8,w9};
    const int    ns[10] = {216,576,1152,4608,16128,52416,194688,11648,52416,28080};
    int L = base + blockIdx.x;
    const float* w = ws[L];
    int n = ns[L];
    int tid = threadIdx.x;
    float m = 0.f;
    const float4* w4p = (const float4*)w;
    for (int i = tid; i < (n >> 2); i += blockDim.x) {
        float4 v = w4p[i];
        m = fmaxf(m, fmaxf(fmaxf(fabsf(v.x), fabsf(v.y)),
                           fmaxf(fabsf(v.z), fabsf(v.w))));
    }
    __shared__ float red[256];
    red[tid] = m;
    __syncthreads();
    for (int s = 128; s > 0; s >>= 1) {
        if (tid < s) red[tid] = fmaxf(red[tid], red[tid + s]);
        __syncthreads();
    }
    if (tid == 0) g_scale[L] = fmaxf(red[0], 1e-8f);
}

// ----------------------------------------------------------------------------
// Build sparse lists. Block L (0..9): L==0 -> conv1 +/- offset lists;
// else per-cout {off, word} entries for nonzero weight words (sorted by k).
// ----------------------------------------------------------------------------
__global__ void prep_sparse(const float* w0, const float* w1, const float* w2,
                            const float* w3, const float* w4, const float* w5,
                            const float* w6, const float* w7, const float* w8,
                            const float* w9) {
    const float* ws[10] = {w0,w1,w2,w3,w4,w5,w6,w7,w8,w9};
    const int couts[10] = {8,8,16,32,56,104,208,56,104,30};
    const int  cins[10] = {3,8,8,16,32,56,104,208,56,104};
    const int   kks[10] = {9,9,9,9,9,9,9,1,9,9};
    const int  maxe[10] = {0,18,18,36,72,126,234,52,126,234};
    const int    eb[10] = {0,0,144,432,1584,5616,18720,67392,70304,83408};
    const int    cb[10] = {0,0,8,24,56,112,216,424,480,584};

    int L = blockIdx.x;
    int co = threadIdx.x;
    if (co >= couts[L]) return;
    float s = g_scale[L];

    if (L == 0) {
        const float* w = ws[0];
        int pc = 0, mc = 0;
        for (int ci = 0; ci < 3; ci++)
            for (int ky = 0; ky < 3; ky++)
                for (int kx = 0; kx < 3; kx++) {
                    float v = w[((co * 3 + ci) * 3 + ky) * 3 + kx] / s;
                    int q = (int)rintf(fminf(fmaxf(v, -1.f), 1.f));
                    unsigned short off = (unsigned short)(ci * 340 + ky * 34 + kx);
                    if (q > 0) g_c1p[co * 32 + pc++] = off;
                    else if (q < 0) g_c1m[co * 32 + mc++] = off;
                }
        g_c1cnt[co] = pc;
        g_c1cnt[8 + co] = mc;
        return;
    }

    const float* w = ws[L];
    int cin = cins[L], kk = kks[L], W4 = cin / 4;
    int2* elist = g_entries + eb[L] + co * maxe[L];
    int cnt = 0;
    for (int k = 0; k < W4; k++) {
        for (int t = 0; t < kk; t++) {
            uint32_t word = 0;
            for (int b = 0; b < 4; b++) {
                int ci = 4 * k + b;
                float v = w[(co * cin + ci) * kk + t] / s;
                int q = (int)rintf(fminf(fmaxf(v, -1.f), 1.f));
                word |= ((uint32_t)(uint8_t)(int8_t)q) << (8 * b);
            }
            if (word) {
                int off;
                if (L <= 4) {                       // pool layers: tile 18x34
                    int ky = t / 3, kx = t % 3;
                    off = k * 612 + ky * 34 + kx;
                } else if (L == 7) {                // 1x1: global planar
                    off = k * 400;
                } else {                            // 20x20 3x3: tile 22x22
                    int ky = t / 3, kx = t % 3;
                    off = k * 484 + ky * 22 + kx;
                }
                elist[cnt++] = make_int2(off, (int)word);
            }
        }
    }
    g_cnt[cb[L] + co] = cnt;
}

// ----------------------------------------------------------------------------
// conv1 sparse: s * sum(+/- x), smem float tile, quant_relu + 2x2 pool.
// 256 thr: warp w -> cout-pair (w&3), pixel-half (w>>2); lane -> pooled px.
// ----------------------------------------------------------------------------
__global__ __launch_bounds__(256) void conv1_sp(const float* __restrict__ x,
                                                uint32_t* __restrict__ out) {
    __shared__ float s_x[1020];   // 3ch x 10rows x 34cols

    const int t = threadIdx.x;
    const int n = blockIdx.z;
    const int px0 = blockIdx.x * 16, py0 = blockIdx.y * 4;

    for (int i = t; i < 1020; i += 256) {
        int ch = i / 340, rem = i % 340, r = rem / 34, c = rem % 34;
        int gy = 2 * py0 - 1 + r;
        int gx = 2 * px0 - 1 + c;
        float v = 0.f;
        if ((unsigned)gx < 640u && (unsigned)gy < 640u)
            v = __ldg(x + ((size_t)(n * 3 + ch) * 640 + gy) * 640 + gx);
        s_x[i] = v;
    }
    __syncthreads();

    const int warp = t >> 5, lane = t & 31;
    const int pair = warp & 3, half = warp >> 2;
    const int pid = half * 32 + lane;
    const int tx = pid & 15, ty = pid >> 4;
    const int tb = (2 * ty) * 34 + 2 * tx;

    float s = g_scale[0];
    uint32_t codes[2];
#pragma unroll
    for (int cc = 0; cc < 2; cc++) {
        int co = pair * 2 + cc;
        float a0 = 0.f, a1 = 0.f, a2 = 0.f, a3 = 0.f;
        int pcnt = g_c1cnt[co], mcnt = g_c1cnt[8 + co];
        const unsigned short* pl = &g_c1p[co * 32];
        const unsigned short* ml = &g_c1m[co * 32];
        for (int i = 0; i < pcnt; i++) {
            int b = (int)__ldg(pl + i) + tb;
            a0 += s_x[b];      a1 += s_x[b + 1];
            a2 += s_x[b + 34]; a3 += s_x[b + 35];
        }
        for (int i = 0; i < mcnt; i++) {
            int b = (int)__ldg(ml + i) + tb;
            a0 -= s_x[b];      a1 -= s_x[b + 1];
            a2 -= s_x[b + 34]; a3 -= s_x[b + 35];
        }
        float m = fmaxf(fmaxf(a0, a1), fmaxf(a2, a3));
        codes[cc] = (uint32_t)(int)rintf(fminf(fmaxf(s * m * 0.5f, 0.f), 3.f));
    }

    uint32_t v16 = codes[0] | (codes[1] << 8);
    size_t widx = ((size_t)n * 2 + (pair >> 1)) * 102400
                + (size_t)(py0 + ty) * 320 + (px0 + tx);
    *(uint16_t*)((uint8_t*)out + widx * 4 + (pair & 1) * 2) = (uint16_t)v16;
}

// ----------------------------------------------------------------------------
// Sparse int conv 3x3 + quant_relu + 2x2 pool. smem word tile 18x34 per plane
// (zero halo). 128 thr = 16x8 pooled px tile; 4 couts per block (z).
// ----------------------------------------------------------------------------
template <int W4>
__global__ __launch_bounds__(128) void convpool_sp(const uint32_t* __restrict__ in,
                                                   int sidx, uint32_t* __restrict__ out,
                                                   int S, int tilesx,
                                                   int ebase, int cbase, int maxe,
                                                   int outW4) {
    __shared__ uint32_t tile[W4 * 612];   // 18 rows x 34 cols
    const int t = threadIdx.x;
    const int n = blockIdx.y;
    const int bx = blockIdx.x % tilesx, by = blockIdx.x / tilesx;
    const int cx0 = bx * 32, cy0 = by * 16;
    const int HW = S * S;
    const uint32_t* base = in + (size_t)n * W4 * HW;

    for (int i = t; i < W4 * 612; i += 128) {
        int k = i / 612, rem = i % 612, r = rem / 34, c = rem % 34;
        int gy = cy0 - 1 + r, gx = cx0 - 1 + c;
        uint32_t v = 0;
        if ((unsigned)gy < (unsigned)S && (unsigned)gx < (unsigned)S)
            v = __ldg(base + k * HW + gy * S + gx);
        tile[i] = v;
    }
    __syncthreads();

    const int tx = t & 15, ty = t >> 4;
    const int tb = (2 * ty) * 34 + 2 * tx;

    int acc[4][4];
#pragma unroll
    for (int co = 0; co < 4; co++)
#pragma unroll
        for (int j = 0; j < 4; j++) acc[co][j] = 0;

#pragma unroll
    for (int co = 0; co < 4; co++) {
        int cidx = blockIdx.z * 4 + co;
        int cnt = g_cnt[cbase + cidx];
        const int2* e = g_entries + ebase + cidx * maxe;
        for (int i = 0; i < cnt; i++) {
            int2 ev = __ldg(e + i);
            int b = ev.x + tb;
            acc[co][0] = __dp4a((int)tile[b],      ev.y, acc[co][0]);
            acc[co][1] = __dp4a((int)tile[b + 1],  ev.y, acc[co][1]);
            acc[co][2] = __dp4a((int)tile[b + 34], ev.y, acc[co][2]);
            acc[co][3] = __dp4a((int)tile[b + 35], ev.y, acc[co][3]);
        }
    }

    const int P = S >> 1;
    int py = by * 8 + ty, px = bx * 16 + tx;
    if (py >= P || px >= P) return;
    float s = g_scale[sidx];
    uint32_t w = 0;
#pragma unroll
    for (int co = 0; co < 4; co++) {
        int m = max(max(acc[co][0], acc[co][1]), max(acc[co][2], acc[co][3]));
        w |= ((uint32_t)(int)rintf(fminf(fmaxf(s * (float)m, 0.f), 3.f))) << (co * 8);
    }
    out[((size_t)n * outW4 + blockIdx.z) * (P * P) + py * P + px] = w;
}

// ----------------------------------------------------------------------------
// Sparse int conv 3x3 on 20x20 (no pool), phase-split over channel planes.
// KSP planes per phase (static smem KSP*484 words <= 25KB). Entries are
// sorted by plane, so each phase consumes a warp-uniform prefix.
// thread t<100: row y=t/5, cols {m, m+5, m+10, m+15}; NCO couts per block.
// ----------------------------------------------------------------------------
template <int W4, int NCO, int KSP>
__global__ __launch_bounds__(128) void conv20_sp(const uint32_t* __restrict__ in,
                                                 int sidx, uint32_t* __restrict__ out,
                                                 int ebase, int cbase, int maxe,
                                                 int outW4) {
    __shared__ uint32_t tile[KSP * 484];
    const int t = threadIdx.x;
    const int n = blockIdx.y;
    const uint32_t* base = in + (size_t)n * W4 * 400;
    const int y = t / 5, m = t % 5;
    const int tb = y * 22 + m;

    int acc[NCO][4];
    int idx[NCO], cnt[NCO];
    const int2* eptr[NCO];
#pragma unroll
    for (int co = 0; co < NCO; co++) {
        int cidx = blockIdx.z * NCO + co;
        cnt[co] = g_cnt[cbase + cidx];
        eptr[co] = g_entries + ebase + cidx * maxe;
        idx[co] = 0;
#pragma unroll
        for (int j = 0; j < 4; j++) acc[co][j] = 0;
    }

#pragma unroll
    for (int ph = 0; ph < W4; ph += KSP) {
        const int kmax = (ph + KSP < W4) ? ph + KSP : W4;
        const int nw = (kmax - ph) * 484;
        for (int i = t; i < nw; i += 128) {
            int k = i / 484, rem = i % 484, r = rem / 22, c = rem % 22;
            int gy = r - 1, gx = c - 1;
            uint32_t v = 0;
            if ((unsigned)gy < 20u && (unsigned)gx < 20u)
                v = __ldg(base + (ph + k) * 400 + gy * 20 + gx);
            tile[i] = v;
        }
        __syncthreads();
        if (t < 100) {
            const int lim = kmax * 484;
            const int shift = ph * 484 - tb;
#pragma unroll
            for (int co = 0; co < NCO; co++) {
                int i = idx[co];
                while (i < cnt[co]) {
                    int2 ev = __ldg(eptr[co] + i);
                    if (ev.x >= lim) break;
                    int b = ev.x - shift;
                    acc[co][0] = __dp4a((int)tile[b],      ev.y, acc[co][0]);
                    acc[co][1] = __dp4a((int)tile[b + 5],  ev.y, acc[co][1]);
                    acc[co][2] = __dp4a((int)tile[b + 10], ev.y, acc[co][2]);
                    acc[co][3] = __dp4a((int)tile[b + 15], ev.y, acc[co][3]);
                    i++;
                }
                idx[co] = i;
            }
        }
        __syncthreads();
    }
    if (t >= 100) return;

    float s = g_scale[sidx];
#pragma unroll
    for (int g4 = 0; g4 < NCO / 4; g4++) {
        int plane = blockIdx.z * (NCO / 4) + g4;
#pragma unroll
        for (int j = 0; j < 4; j++) {
            uint32_t w = 0;
#pragma unroll
            for (int co = 0; co < 4; co++) {
                int cc = g4 * 4 + co;
                w |= ((uint32_t)(int)rintf(
                        fminf(fmaxf(s * (float)acc[cc][j], 0.f), 3.f))) << (co * 8);
            }
            out[((size_t)n * outW4 + plane) * 400 + y * 20 + m + 5 * j] = w;
        }
    }
}

// ----------------------------------------------------------------------------
// Sparse 1x1 conv (L8): direct global loads. thread t<100:
// px {t, t+100, t+200, t+300}; 8 couts.
// ----------------------------------------------------------------------------
__global__ __launch_bounds__(128) void conv1x1_sp(const uint32_t* __restrict__ in,
                                                  int sidx, uint32_t* __restrict__ out,
                                                  int ebase, int cbase, int maxe,
                                                  int outW4) {
    const int t = threadIdx.x;
    if (t >= 100) return;
    const int n = blockIdx.y;
    const uint32_t* base = in + (size_t)n * 52 * 400;

    int acc[8][4];
#pragma unroll
    for (int co = 0; co < 8; co++)
#pragma unroll
        for (int j = 0; j < 4; j++) acc[co][j] = 0;

#pragma unroll
    for (int co = 0; co < 8; co++) {
        int cidx = blockIdx.z * 8 + co;
        int cnt = g_cnt[cbase + cidx];
        const int2* e = g_entries + ebase + cidx * maxe;
        for (int i = 0; i < cnt; i++) {
            int2 ev = __ldg(e + i);
            const uint32_t* p = base + ev.x + t;
            acc[co][0] = __dp4a((int)__ldg(p),       ev.y, acc[co][0]);
            acc[co][1] = __dp4a((int)__ldg(p + 100), ev.y, acc[co][1]);
            acc[co][2] = __dp4a((int)__ldg(p + 200), ev.y, acc[co][2]);
            acc[co][3] = __dp4a((int)__ldg(p + 300), ev.y, acc[co][3]);
        }
    }

    float s = g_scale[sidx];
#pragma unroll
    for (int g4 = 0; g4 < 2; g4++) {
        int plane = blockIdx.z * 2 + g4;
#pragma unroll
        for (int j = 0; j < 4; j++) {
            uint32_t w = 0;
#pragma unroll
            for (int co = 0; co < 4; co++) {
                int cc = g4 * 4 + co;
                w |= ((uint32_t)(int)rintf(
                        fminf(fmaxf(s * (float)acc[cc][j], 0.f), 3.f))) << (co * 8);
            }
            out[((size_t)n * outW4 + plane) * 400 + t + 100 * j] = w;
        }
    }
}

// ----------------------------------------------------------------------------
// L10 sparse: 3x3 104->30 + quant_hardtanh, fp32 NCHW out. Two-phase (13+13
// planes), NCO=6, z=5.
// ----------------------------------------------------------------------------
__global__ __launch_bounds__(128) void conv10_sp(const uint32_t* __restrict__ in,
                                                 float* __restrict__ out,
                                                 int ebase, int cbase, int maxe) {
    __shared__ uint32_t tile[13 * 484];
    const int t = threadIdx.x;
    const int n = blockIdx.y;
    const uint32_t* base = in + (size_t)n * 26 * 400;
    const int y = t / 5, m = t % 5;
    const int tb = y * 22 + m;

    int acc[6][4];
    int idx[6], cnt[6];
    const int2* eptr[6];
#pragma unroll
    for (int co = 0; co < 6; co++) {
        int cidx = blockIdx.z * 6 + co;
        cnt[co] = g_cnt[cbase + cidx];
        eptr[co] = g_entries + ebase + cidx * maxe;
        idx[co] = 0;
#pragma unroll
        for (int j = 0; j < 4; j++) acc[co][j] = 0;
    }

#pragma unroll
    for (int ph = 0; ph < 26; ph += 13) {
        const int nw = 13 * 484;
        for (int i = t; i < nw; i += 128) {
            int k = i / 484, rem = i % 484, r = rem / 22, c = rem % 22;
            int gy = r - 1, gx = c - 1;
            uint32_t v = 0;
            if ((unsigned)gy < 20u && (unsigned)gx < 20u)
                v = __ldg(base + (ph + k) * 400 + gy * 20 + gx);
            tile[i] = v;
        }
        __syncthreads();
        if (t < 100) {
            const int lim = (ph + 13) * 484;
            const int shift = ph * 484 - tb;
#pragma unroll
            for (int co = 0; co < 6; co++) {
                int i = idx[co];
                while (i < cnt[co]) {
                    int2 ev = __ldg(eptr[co] + i);
                    if (ev.x >= lim) break;
                    int b = ev.x - shift;
                    acc[co][0] = __dp4a((int)tile[b],      ev.y, acc[co][0]);
                    acc[co][1] = __dp4a((int)tile[b + 5],  ev.y, acc[co][1]);
                    acc[co][2] = __dp4a((int)tile[b + 10], ev.y, acc[co][2]);
                    acc[co][3] = __dp4a((int)tile[b + 15], ev.y, acc[co][3]);
                    i++;
                }
                idx[co] = i;
            }
        }
        __syncthreads();
    }
    if (t >= 100) return;

    float s = g_scale[9];
#pragma unroll
    for (int co = 0; co < 6; co++) {
        int cg = blockIdx.z * 6 + co;
#pragma unroll
        for (int j = 0; j < 4; j++) {
            float v = 2.f * s * (float)acc[co][j];
            float tt = fminf(fmaxf(v, 0.f), 1.f);
            out[((size_t)(n * 30 + cg)) * 400 + y * 20 + m + 5 * j] =
                rintf(tt * 255.f) * (1.f / 255.f);
        }
    }
}

// ----------------------------------------------------------------------------
// Launch
// ----------------------------------------------------------------------------
extern "C" void kernel_launch(void* const* d_in, const int* in_sizes, int n_in,
                              void* d_out, int out_size) {
    const float* x = (const float*)d_in[0];
    const float* w[10];
    for (int i = 0; i < 10; i++) w[i] = (const float*)d_in[1 + i];

    void *p_a1, *p_a2, *p_a3, *p_a4, *p_a5, *p_a6, *p_a7, *p_a8, *p_a9;
    cudaGetSymbolAddress(&p_a1, g_act1);
    cudaGetSymbolAddress(&p_a2, g_act2);
    cudaGetSymbolAddress(&p_a3, g_act3);
    cudaGetSymbolAddress(&p_a4, g_act4);
    cudaGetSymbolAddress(&p_a5, g_act5);
    cudaGetSymbolAddress(&p_a6, g_act6);
    cudaGetSymbolAddress(&p_a7, g_act7);
    cudaGetSymbolAddress(&p_a8, g_act8);
    cudaGetSymbolAddress(&p_a9, g_act9);

    const uint32_t *a1 = (const uint32_t*)p_a1, *a2 = (const uint32_t*)p_a2,
                   *a3 = (const uint32_t*)p_a3, *a4 = (const uint32_t*)p_a4,
                   *a5 = (const uint32_t*)p_a5, *a6 = (const uint32_t*)p_a6,
                   *a7 = (const uint32_t*)p_a7, *a8 = (const uint32_t*)p_a8,
                   *a9 = (const uint32_t*)p_a9;

    absmax5<<<5, 256>>>(w[0], w[1], w[2], w[3], w[4], w[5], w[6], w[7], w[8], w[9], 0);
    absmax5<<<5, 256>>>(w[0], w[1], w[2], w[3], w[4], w[5], w[6], w[7], w[8], w[9], 5);
    prep_sparse<<<10, 256>>>(w[0], w[1], w[2], w[3], w[4], w[5], w[6], w[7], w[8], w[9]);

    // 4th launch -> ncu capture slot
    conv1_sp<<<dim3(20, 80, 16), 256>>>(x, (uint32_t*)p_a1);

    // L2: S=320, P=160, tiles 10x20, z=2
    convpool_sp<2><<<dim3(200, 16, 2), 128>>>(a1, 1, (uint32_t*)p_a2,
                                              320, 10, 0, 0, 18, 2);
    // L3: S=160, P=80, tiles 5x10, z=4
    convpool_sp<2><<<dim3(50, 16, 4), 128>>>(a2, 2, (uint32_t*)p_a3,
                                             160, 5, 144, 8, 18, 4);
    // L4: S=80, P=40, tiles 3x5, z=8
    convpool_sp<4><<<dim3(15, 16, 8), 128>>>(a3, 3, (uint32_t*)p_a4,
                                             80, 3, 432, 24, 36, 8);
    // L5: S=40, P=20, tiles 2x3, z=14
    convpool_sp<8><<<dim3(6, 16, 14), 128>>>(a4, 4, (uint32_t*)p_a5,
                                             40, 2, 1584, 56, 72, 14);
    // L6: 56->104, single phase (14 planes, 27KB)
    conv20_sp<14, 8, 14><<<dim3(1, 16, 13), 128>>>(a5, 5, (uint32_t*)p_a6,
                                                   5616, 112, 126, 26);
    // L7: 104->208, two phases (13+13 planes, 25KB)
    conv20_sp<26, 8, 13><<<dim3(1, 16, 26), 128>>>(a6, 6, (uint32_t*)p_a7,
                                                   18720, 216, 234, 52);
    // L8: 1x1 208->56
    conv1x1_sp<<<dim3(1, 16, 7), 128>>>(a7, 7, (uint32_t*)p_a8, 67392, 424, 52, 14);
    // L9: 56->104
    conv20_sp<14, 8, 14><<<dim3(1, 16, 13), 128>>>(a8, 8, (uint32_t*)p_a9,
                                                   70304, 480, 126, 26);
    // L10: 104->30, two phases
    conv10_sp<<<dim3(1, 16, 5), 128>>>(a9, (float*)d_out, 83408, 584, 234);
}

// round 8
// speedup vs baseline: 1.3655x; 1.3655x over previous
#include <cuda_runtime.h>
#include <cstdint>

// ============================================================================
// QuantizedYOLOv3Tiny — round 8 (re-bench of round 7; prior run died on
// container infra, not kernel). Int layers: round-4 dense dp4a kernels.
// conv1: sparse +/- tap lists over a shifted-pair smem tile; each tap =
// 2x LDS.64 + 2x add.rn.f32x2 per cout.
// ============================================================================

#define ALIGN16 __align__(16)

__device__ float g_scale[10];

__device__ ALIGN16 int8_t g_w2q[576];
__device__ ALIGN16 int8_t g_w3q[1152];
__device__ ALIGN16 int8_t g_w4q[4608];
__device__ ALIGN16 int8_t g_w5q[16128];
__device__ ALIGN16 int8_t g_w6q[52416];
__device__ ALIGN16 int8_t g_w7q[194688];
__device__ ALIGN16 int8_t g_w8q[11648];
__device__ ALIGN16 int8_t g_w9q[52416];
__device__ ALIGN16 int8_t g_w10q[28080];

__device__ unsigned short g_c1p[8 * 32], g_c1m[8 * 32];
__device__ int g_c1cnt[16];

__device__ ALIGN16 uint32_t g_act1[16*2*320*320];
__device__ ALIGN16 uint32_t g_act2[16*2*160*160];
__device__ ALIGN16 uint32_t g_act3[16*4*80*80];
__device__ ALIGN16 uint32_t g_act4[16*8*40*40];
__device__ ALIGN16 uint32_t g_act5[16*14*20*20];
__device__ ALIGN16 uint32_t g_act6[16*26*20*20];
__device__ ALIGN16 uint32_t g_act7[16*52*20*20];
__device__ ALIGN16 uint32_t g_act8[16*14*20*20];
__device__ ALIGN16 uint32_t g_act9[16*26*20*20];

// ----------------------------------------------------------------------------
// absmax per layer (block L)
// ----------------------------------------------------------------------------
__global__ void absmax10(const float* w0, const float* w1, const float* w2,
                         const float* w3, const float* w4, const float* w5,
                         const float* w6, const float* w7, const float* w8,
                         const float* w9) {
    const float* ws[10] = {w0,w1,w2,w3,w4,w5,w6,w7,w8,w9};
    const int    ns[10] = {216,576,1152,4608,16128,52416,194688,11648,52416,28080};
    int L = blockIdx.x;
    const float* w = ws[L];
    int n = ns[L];
    int tid = threadIdx.x;
    float m = 0.f;
    const float4* w4p = (const float4*)w;
    for (int i = tid; i < (n >> 2); i += blockDim.x) {
        float4 v = w4p[i];
        m = fmaxf(m, fmaxf(fmaxf(fabsf(v.x), fabsf(v.y)),
                           fmaxf(fabsf(v.z), fabsf(v.w))));
    }
    __shared__ float red[256];
    red[tid] = m;
    __syncthreads();
    for (int s = 128; s > 0; s >>= 1) {
        if (tid < s) red[tid] = fmaxf(red[tid], red[tid + s]);
        __syncthreads();
    }
    if (tid == 0) g_scale[L] = fmaxf(red[0], 1e-8f);
}

// ----------------------------------------------------------------------------
// Wide repack for int layers 2..10 (grid-strided)
// ----------------------------------------------------------------------------
__global__ void repack_all(const float* w1, const float* w2,
                           const float* w3, const float* w4, const float* w5,
                           const float* w6, const float* w7, const float* w8,
                           const float* w9) {
    const float* ws[9] = {w1,w2,w3,w4,w5,w6,w7,w8,w9};
    const int    ns[9] = {576,1152,4608,16128,52416,194688,11648,52416,28080};
    const int  cins[9] = {8,8,16,32,56,104,208,56,104};
    const int   kks[9] = {9,9,9,9,9,9,1,9,9};
    int8_t* wqs[9] = {g_w2q, g_w3q, g_w4q, g_w5q, g_w6q,
                      g_w7q, g_w8q, g_w9q, g_w10q};

    int gid = blockIdx.x * blockDim.x + threadIdx.x;
    int L = 0, off = gid;
    while (L < 9 && off >= ns[L]) { off -= ns[L]; L++; }
    if (L >= 9) return;

    float s = g_scale[L + 1];
    const float* w = ws[L];
    int cin = cins[L], kk = kks[L];
    int co = off / (cin * kk);
    int rem = off % (cin * kk);
    int ci = rem / kk;
    int t  = rem % kk;
    float v = w[off] / s;
    int q = (int)rintf(fminf(fmaxf(v, -1.f), 1.f));
    wqs[L][(co * kk + t) * cin + ci] = (int8_t)q;
}

// ----------------------------------------------------------------------------
// conv1 sign lists: offsets into a 3ch x 10row x 34col tile.
// ----------------------------------------------------------------------------
__global__ void prep_c1(const float* __restrict__ w) {
    int co = threadIdx.x;
    if (co >= 8) return;
    float s = g_scale[0];
    int pc = 0, mc = 0;
    for (int ci = 0; ci < 3; ci++)
        for (int ky = 0; ky < 3; ky++)
            for (int kx = 0; kx < 3; kx++) {
                float v = w[((co * 3 + ci) * 3 + ky) * 3 + kx] / s;
                int q = (int)rintf(fminf(fmaxf(v, -1.f), 1.f));
                unsigned short off = (unsigned short)(ci * 340 + ky * 34 + kx);
                if (q > 0) g_c1p[co * 32 + pc++] = off;
                else if (q < 0) g_c1m[co * 32 + mc++] = off;
            }
    g_c1cnt[co] = pc;
    g_c1cnt[8 + co] = mc;
}

// ----------------------------------------------------------------------------
// conv1 sparse v2: packed f32x2 accumulate over shifted-pair smem tile.
// 256 thr: warp -> cout-pair (warp&3) + pixel-half (warp>>2); lane -> px.
// ----------------------------------------------------------------------------
__device__ __forceinline__ void add2(unsigned long long& acc, unsigned long long v) {
    asm("add.rn.f32x2 %0, %0, %1;" : "+l"(acc) : "l"(v));
}
__device__ __forceinline__ void unpack2(unsigned long long v, float& lo, float& hi) {
    uint32_t a, b;
    asm("mov.b64 {%0, %1}, %2;" : "=r"(a), "=r"(b) : "l"(v));
    lo = __uint_as_float(a);
    hi = __uint_as_float(b);
}

__global__ __launch_bounds__(256) void conv1_sp(const float* __restrict__ x,
                                                uint32_t* __restrict__ out) {
    __shared__ float s_tmp[1021];                 // 3*10*34 + guard
    __shared__ unsigned long long s_x2[1020];     // shifted pairs (v[i], v[i+1])

    const int t = threadIdx.x;
    const int n = blockIdx.z;
    const int px0 = blockIdx.x * 16, py0 = blockIdx.y * 4;

    for (int i = t; i < 1020; i += 256) {
        int ch = i / 340, rem = i % 340, r = rem / 34, c = rem % 34;
        int gy = 2 * py0 - 1 + r;
        int gx = 2 * px0 - 1 + c;
        float v = 0.f;
        if ((unsigned)gx < 640u && (unsigned)gy < 640u)
            v = __ldg(x + ((size_t)(n * 3 + ch) * 640 + gy) * 640 + gx);
        s_tmp[i] = v;
    }
    if (t == 0) s_tmp[1020] = 0.f;
    __syncthreads();
    for (int i = t; i < 1020; i += 256) {
        uint32_t lo = __float_as_uint(s_tmp[i]);
        uint32_t hi = __float_as_uint(s_tmp[i + 1]);
        s_x2[i] = ((unsigned long long)hi << 32) | lo;
    }
    __syncthreads();

    const int warp = t >> 5, lane = t & 31;
    const int pair = warp & 3, half = warp >> 2;
    const int pid = half * 32 + lane;
    const int tx = pid & 15, ty = pid >> 4;
    const int tb = (2 * ty) * 34 + 2 * tx;

    float s = g_scale[0];
    uint32_t codes[2];
#pragma unroll
    for (int cc = 0; cc < 2; cc++) {
        int co = pair * 2 + cc;
        unsigned long long ap01 = 0ull, ap23 = 0ull, am01 = 0ull, am23 = 0ull;
        int pcnt = g_c1cnt[co], mcnt = g_c1cnt[8 + co];
        const unsigned short* pl = &g_c1p[co * 32];
        const unsigned short* ml = &g_c1m[co * 32];
        for (int i = 0; i < pcnt; i++) {
            int b = (int)__ldg(pl + i) + tb;
            add2(ap01, s_x2[b]);
            add2(ap23, s_x2[b + 34]);
        }
        for (int i = 0; i < mcnt; i++) {
            int b = (int)__ldg(ml + i) + tb;
            add2(am01, s_x2[b]);
            add2(am23, s_x2[b + 34]);
        }
        float p0, p1, p2, p3, m0, m1, m2, m3;
        unpack2(ap01, p0, p1);
        unpack2(ap23, p2, p3);
        unpack2(am01, m0, m1);
        unpack2(am23, m2, m3);
        float a0 = p0 - m0, a1 = p1 - m1, a2 = p2 - m2, a3 = p3 - m3;
        float mx = fmaxf(fmaxf(a0, a1), fmaxf(a2, a3));
        codes[cc] = (uint32_t)(int)rintf(fminf(fmaxf(s * mx * 0.5f, 0.f), 3.f));
    }

    uint32_t v16 = codes[0] | (codes[1] << 8);
    size_t widx = ((size_t)n * 2 + (pair >> 1)) * 102400
                + (size_t)(py0 + ty) * 320 + (px0 + tx);
    *(uint16_t*)((uint8_t*)out + widx * 4 + (pair & 1) * 2) = (uint16_t)v16;
}

// ----------------------------------------------------------------------------
// Int conv 3x3 + quant_relu + 2x2 pool (round-4 dense). 4 conv cols x 4 couts.
// ----------------------------------------------------------------------------
template <int CIN>
__global__ __launch_bounds__(128) void convpool2(const uint32_t* __restrict__ in,
                                                 const int8_t* __restrict__ wq,
                                                 int sidx, uint32_t* __restrict__ out,
                                                 int S, int outW4) {
    constexpr int W4 = CIN / 4;
    __shared__ int ws[4 * 9 * W4];
    const int* wg = (const int*)wq + blockIdx.z * (4 * 9 * W4);
    for (int i = threadIdx.x; i < 4 * 9 * W4; i += 128) ws[i] = wg[i];
    __syncthreads();

    const int P = S >> 1, Ph = P >> 1, HW = S * S;
    int p = blockIdx.x * 128 + threadIdx.x;
    if (p >= P * Ph) return;
    int py = p / Ph, pxp = p % Ph;
    int n = blockIdx.y;

    int acc[2][4][4] = {};
    const uint32_t* base = in + (size_t)n * W4 * HW;

#pragma unroll
    for (int r = 0; r < 4; r++) {
        int y = 2 * py + r - 1;
        if ((unsigned)y >= (unsigned)S) continue;
#pragma unroll
        for (int k = 0; k < W4; k++) {
            const uint32_t* rp = base + k * HW + y * S;
            int a[6];
#pragma unroll
            for (int c = 0; c < 6; c++) {
                int xx = 4 * pxp - 1 + c;
                a[c] = ((unsigned)xx < (unsigned)S) ? (int)__ldg(rp + xx) : 0;
            }
#pragma unroll
            for (int ky = 0; ky < 3; ky++) {
                int dy = r - ky;
                if (dy < 0 || dy > 1) continue;
#pragma unroll
                for (int kx = 0; kx < 3; kx++) {
#pragma unroll
                    for (int co = 0; co < 4; co++) {
                        int w = ws[(co * 9 + ky * 3 + kx) * W4 + k];
#pragma unroll
                        for (int j = 0; j < 4; j++)
                            acc[dy][j][co] = __dp4a(a[j + kx], w, acc[dy][j][co]);
                    }
                }
            }
        }
    }

    float s = g_scale[sidx];
    uint32_t w0 = 0, w1 = 0;
#pragma unroll
    for (int co = 0; co < 4; co++) {
        int m0 = max(max(acc[0][0][co], acc[0][1][co]),
                     max(acc[1][0][co], acc[1][1][co]));
        int m1 = max(max(acc[0][2][co], acc[0][3][co]),
                     max(acc[1][2][co], acc[1][3][co]));
        w0 |= ((uint32_t)(int)rintf(fminf(fmaxf(s * (float)m0, 0.f), 3.f))) << (co * 8);
        w1 |= ((uint32_t)(int)rintf(fminf(fmaxf(s * (float)m1, 0.f), 3.f))) << (co * 8);
    }
    uint32_t* op = out + ((size_t)n * outW4 + blockIdx.z) * (P * P) + py * P + 2 * pxp;
    op[0] = w0;
    op[1] = w1;
}

// ----------------------------------------------------------------------------
// Int conv 3x3 on 20x20 (round-4 dense). 4 columns x NCO couts.
// ----------------------------------------------------------------------------
template <int CIN, int NCO>
__global__ __launch_bounds__(128) void conv3s(const uint32_t* __restrict__ in,
                                              const int8_t* __restrict__ wq,
                                              int sidx, uint32_t* __restrict__ out,
                                              int outW4) {
    constexpr int W4 = CIN / 4;
    __shared__ int ws[NCO * 9 * W4];
    const int* wg = (const int*)wq + blockIdx.z * (NCO * 9 * W4);
    for (int i = threadIdx.x; i < NCO * 9 * W4; i += 128) ws[i] = wg[i];
    __syncthreads();

    int t = threadIdx.x;
    if (t >= 100) return;
    int py = t / 5, px0 = (t % 5) * 4;
    int n = blockIdx.y;

    int acc[4][NCO];
#pragma unroll
    for (int j = 0; j < 4; j++)
#pragma unroll
        for (int co = 0; co < NCO; co++) acc[j][co] = 0;

    const uint32_t* base = in + (size_t)n * W4 * 400;

#pragma unroll
    for (int ky = 0; ky < 3; ky++) {
        int y = py + ky - 1;
        if ((unsigned)y >= 20u) continue;
        for (int k = 0; k < W4; k++) {
            const uint32_t* rp = base + k * 400 + y * 20;
            int a[6];
#pragma unroll
            for (int c = 0; c < 6; c++) {
                int xx = px0 - 1 + c;
                a[c] = ((unsigned)xx < 20u) ? (int)__ldg(rp + xx) : 0;
            }
#pragma unroll
            for (int kx = 0; kx < 3; kx++) {
#pragma unroll
                for (int co = 0; co < NCO; co++) {
                    int w = ws[(co * 9 + ky * 3 + kx) * W4 + k];
#pragma unroll
                    for (int j = 0; j < 4; j++)
                        acc[j][co] = __dp4a(a[j + kx], w, acc[j][co]);
                }
            }
        }
    }

    float s = g_scale[sidx];
#pragma unroll
    for (int wg4 = 0; wg4 < NCO / 4; wg4++) {
        uint32_t v[4];
#pragma unroll
        for (int j = 0; j < 4; j++) {
            uint32_t b = 0;
#pragma unroll
            for (int co = 0; co < 4; co++) {
                int cc = wg4 * 4 + co;
                b |= ((uint32_t)(int)rintf(fminf(fmaxf(s * (float)acc[j][cc], 0.f), 3.f)))
                     << (co * 8);
            }
            v[j] = b;
        }
        int plane = blockIdx.z * (NCO / 4) + wg4;
        *(uint4*)(out + ((size_t)n * outW4 + plane) * 400 + py * 20 + px0) =
            make_uint4(v[0], v[1], v[2], v[3]);
    }
}

// ----------------------------------------------------------------------------
// Int conv 1x1 on 20x20 (round-4 dense). 4 pixels x NCO couts.
// ----------------------------------------------------------------------------
template <int CIN, int NCO>
__global__ __launch_bounds__(128) void conv1x1s(const uint32_t* __restrict__ in,
                                                const int8_t* __restrict__ wq,
                                                int sidx, uint32_t* __restrict__ out,
                                                int outW4) {
    constexpr int W4 = CIN / 4;
    __shared__ int ws[NCO * W4];
    const int* wg = (const int*)wq + blockIdx.z * (NCO * W4);
    for (int i = threadIdx.x; i < NCO * W4; i += 128) ws[i] = wg[i];
    __syncthreads();

    int t = threadIdx.x;
    if (t >= 100) return;
    int p0 = t * 4;
    int n = blockIdx.y;

    int acc[4][NCO];
#pragma unroll
    for (int j = 0; j < 4; j++)
#pragma unroll
        for (int co = 0; co < NCO; co++) acc[j][co] = 0;

    const uint32_t* base = in + (size_t)n * W4 * 400;
#pragma unroll
    for (int k = 0; k < W4; k++) {
        uint4 av = __ldg((const uint4*)(base + k * 400 + p0));
        int a[4] = {(int)av.x, (int)av.y, (int)av.z, (int)av.w};
#pragma unroll
        for (int co = 0; co < NCO; co++) {
            int w = ws[co * W4 + k];
#pragma unroll
            for (int j = 0; j < 4; j++)
                acc[j][co] = __dp4a(a[j], w, acc[j][co]);
        }
    }

    float s = g_scale[sidx];
#pragma unroll
    for (int wg4 = 0; wg4 < NCO / 4; wg4++) {
        uint32_t v[4];
#pragma unroll
        for (int j = 0; j < 4; j++) {
            uint32_t b = 0;
#pragma unroll
            for (int co = 0; co < 4; co++) {
                int cc = wg4 * 4 + co;
                b |= ((uint32_t)(int)rintf(fminf(fmaxf(s * (float)acc[j][cc], 0.f), 3.f)))
                     << (co * 8);
            }
            v[j] = b;
        }
        int plane = blockIdx.z * (NCO / 4) + wg4;
        *(uint4*)(out + ((size_t)n * outW4 + plane) * 400 + p0) =
            make_uint4(v[0], v[1], v[2], v[3]);
    }
}

// ----------------------------------------------------------------------------
// Layer 10 (round-4 dense): 3x3 104->30 + quant_hardtanh, fp32 NCHW out.
// ----------------------------------------------------------------------------
__global__ __launch_bounds__(128) void conv10_out(const uint32_t* __restrict__ in,
                                                  const int8_t* __restrict__ wq,
                                                  float* __restrict__ out) {
    constexpr int W4 = 26;
    __shared__ int ws[3 * 9 * W4];
    const int* wg = (const int*)wq + blockIdx.z * (3 * 9 * W4);
    for (int i = threadIdx.x; i < 3 * 9 * W4; i += 128) ws[i] = wg[i];
    __syncthreads();

    int t = threadIdx.x;
    if (t >= 100) return;
    int py = t / 5, px0 = (t % 5) * 4;
    int n = blockIdx.y;

    int acc[4][3];
#pragma unroll
    for (int j = 0; j < 4; j++)
#pragma unroll
        for (int co = 0; co < 3; co++) acc[j][co] = 0;

    const uint32_t* base = in + (size_t)n * W4 * 400;
#pragma unroll
    for (int ky = 0; ky < 3; ky++) {
        int y = py + ky - 1;
        if ((unsigned)y >= 20u) continue;
        for (int k = 0; k < W4; k++) {
            const uint32_t* rp = base + k * 400 + y * 20;
            int a[6];
#pragma unroll
            for (int c = 0; c < 6; c++) {
                int xx = px0 - 1 + c;
                a[c] = ((unsigned)xx < 20u) ? (int)__ldg(rp + xx) : 0;
            }
#pragma unroll
            for (int kx = 0; kx < 3; kx++) {
#pragma unroll
                for (int co = 0; co < 3; co++) {
                    int w = ws[(co * 9 + ky * 3 + kx) * W4 + k];
#pragma unroll
                    for (int j = 0; j < 4; j++)
                        acc[j][co] = __dp4a(a[j + kx], w, acc[j][co]);
                }
            }
        }
    }

    float s = g_scale[9];
#pragma unroll
    for (int co = 0; co < 3; co++) {
        float4 v;
        float* vp = (float*)&v;
#pragma unroll
        for (int j = 0; j < 4; j++) {
            float x = 2.f * s * (float)acc[j][co];
            float tt = fminf(fmaxf(x, 0.f), 1.f);
            vp[j] = rintf(tt * 255.f) * (1.f / 255.f);
        }
        int cg = blockIdx.z * 3 + co;
        *(float4*)(out + ((size_t)(n * 30 + cg)) * 400 + py * 20 + px0) = v;
    }
}

// ----------------------------------------------------------------------------
// Launch
// ----------------------------------------------------------------------------
extern "C" void kernel_launch(void* const* d_in, const int* in_sizes, int n_in,
                              void* d_out, int out_size) {
    const float* x = (const float*)d_in[0];
    const float* w[10];
    for (int i = 0; i < 10; i++) w[i] = (const float*)d_in[1 + i];

    void *p_w2, *p_w3, *p_w4, *p_w5, *p_w6, *p_w7, *p_w8, *p_w9, *p_w10;
    void *p_a1, *p_a2, *p_a3, *p_a4, *p_a5, *p_a6, *p_a7, *p_a8, *p_a9;
    cudaGetSymbolAddress(&p_w2, g_w2q);
    cudaGetSymbolAddress(&p_w3, g_w3q);
    cudaGetSymbolAddress(&p_w4, g_w4q);
    cudaGetSymbolAddress(&p_w5, g_w5q);
    cudaGetSymbolAddress(&p_w6, g_w6q);
    cudaGetSymbolAddress(&p_w7, g_w7q);
    cudaGetSymbolAddress(&p_w8, g_w8q);
    cudaGetSymbolAddress(&p_w9, g_w9q);
    cudaGetSymbolAddress(&p_w10, g_w10q);
    cudaGetSymbolAddress(&p_a1, g_act1);
    cudaGetSymbolAddress(&p_a2, g_act2);
    cudaGetSymbolAddress(&p_a3, g_act3);
    cudaGetSymbolAddress(&p_a4, g_act4);
    cudaGetSymbolAddress(&p_a5, g_act5);
    cudaGetSymbolAddress(&p_a6, g_act6);
    cudaGetSymbolAddress(&p_a7, g_act7);
    cudaGetSymbolAddress(&p_a8, g_act8);
    cudaGetSymbolAddress(&p_a9, g_act9);

    const uint32_t *a1 = (const uint32_t*)p_a1, *a2 = (const uint32_t*)p_a2,
                   *a3 = (const uint32_t*)p_a3, *a4 = (const uint32_t*)p_a4,
                   *a5 = (const uint32_t*)p_a5, *a6 = (const uint32_t*)p_a6,
                   *a7 = (const uint32_t*)p_a7, *a8 = (const uint32_t*)p_a8,
                   *a9 = (const uint32_t*)p_a9;

    absmax10<<<10, 256>>>(w[0], w[1], w[2], w[3], w[4], w[5], w[6], w[7], w[8], w[9]);
    repack_all<<<1414, 256>>>(w[1], w[2], w[3], w[4], w[5], w[6], w[7], w[8], w[9]);
    prep_c1<<<1, 32>>>(w[0]);

    conv1_sp<<<dim3(20, 80, 16), 256>>>(x, (uint32_t*)p_a1);

    convpool2<8><<<dim3(100, 16, 2), 128>>>(a1, (const int8_t*)p_w2, 1,
                                            (uint32_t*)p_a2, 320, 2);
    convpool2<8><<<dim3(25, 16, 4), 128>>>(a2, (const int8_t*)p_w3, 2,
                                           (uint32_t*)p_a3, 160, 4);
    convpool2<16><<<dim3(7, 16, 8), 128>>>(a3, (const int8_t*)p_w4, 3,
                                           (uint32_t*)p_a4, 80, 8);
    convpool2<32><<<dim3(2, 16, 14), 128>>>(a4, (const int8_t*)p_w5, 4,
                                            (uint32_t*)p_a5, 40, 14);
    conv3s<56, 4><<<dim3(1, 16, 26), 128>>>(a5, (const int8_t*)p_w6, 5,
                                            (uint32_t*)p_a6, 26);
    conv3s<104, 4><<<dim3(1, 16, 52), 128>>>(a6, (const int8_t*)p_w7, 6,
                                             (uint32_t*)p_a7, 52);
    conv1x1s<208, 4><<<dim3(1, 16, 14), 128>>>(a7, (const int8_t*)p_w8, 7,
                                               (uint32_t*)p_a8, 14);
    conv3s<56, 4><<<dim3(1, 16, 26), 128>>>(a8, (const int8_t*)p_w9, 8,
                                            (uint32_t*)p_a9, 26);
    conv10_out<<<dim3(1, 16, 10), 128>>>(a9, (const int8_t*)p_w10, (float*)d_out);
}

// round 9
// speedup vs baseline: 1.4831x; 1.0862x over previous
#include <cuda_runtime.h>
#include <cstdint>

// ============================================================================
// QuantizedYOLOv3Tiny — round 9
// Int layers: round-4 dense dp4a kernels (proven).
// conv1: round-6 scalar sparse form (measured 90.4us, fastest so far) with
// tap lists promoted to __constant__ (LDC, off the L1 pipe) and offsets
// pre-scaled to bytes.
// ============================================================================

#define ALIGN16 __align__(16)

__device__ float g_scale[10];

__device__ ALIGN16 int8_t g_w2q[576];
__device__ ALIGN16 int8_t g_w3q[1152];
__device__ ALIGN16 int8_t g_w4q[4608];
__device__ ALIGN16 int8_t g_w5q[16128];
__device__ ALIGN16 int8_t g_w6q[52416];
__device__ ALIGN16 int8_t g_w7q[194688];
__device__ ALIGN16 int8_t g_w8q[11648];
__device__ ALIGN16 int8_t g_w9q[52416];
__device__ ALIGN16 int8_t g_w10q[28080];

// staging (device-writable) then copied to __constant__
__device__ unsigned short g_c1p[8 * 32], g_c1m[8 * 32];
__device__ int g_c1cnt[16];

__constant__ unsigned short c_c1p[8 * 32];
__constant__ unsigned short c_c1m[8 * 32];
__constant__ int c_c1cnt[16];

__device__ ALIGN16 uint32_t g_act1[16*2*320*320];
__device__ ALIGN16 uint32_t g_act2[16*2*160*160];
__device__ ALIGN16 uint32_t g_act3[16*4*80*80];
__device__ ALIGN16 uint32_t g_act4[16*8*40*40];
__device__ ALIGN16 uint32_t g_act5[16*14*20*20];
__device__ ALIGN16 uint32_t g_act6[16*26*20*20];
__device__ ALIGN16 uint32_t g_act7[16*52*20*20];
__device__ ALIGN16 uint32_t g_act8[16*14*20*20];
__device__ ALIGN16 uint32_t g_act9[16*26*20*20];

// ----------------------------------------------------------------------------
// absmax per layer (block L)
// ----------------------------------------------------------------------------
__global__ void absmax10(const float* w0, const float* w1, const float* w2,
                         const float* w3, const float* w4, const float* w5,
                         const float* w6, const float* w7, const float* w8,
                         const float* w9) {
    const float* ws[10] = {w0,w1,w2,w3,w4,w5,w6,w7,w8,w9};
    const int    ns[10] = {216,576,1152,4608,16128,52416,194688,11648,52416,28080};
    int L = blockIdx.x;
    const float* w = ws[L];
    int n = ns[L];
    int tid = threadIdx.x;
    float m = 0.f;
    const float4* w4p = (const float4*)w;
    for (int i = tid; i < (n >> 2); i += blockDim.x) {
        float4 v = w4p[i];
        m = fmaxf(m, fmaxf(fmaxf(fabsf(v.x), fabsf(v.y)),
                           fmaxf(fabsf(v.z), fabsf(v.w))));
    }
    __shared__ float red[256];
    red[tid] = m;
    __syncthreads();
    for (int s = 128; s > 0; s >>= 1) {
        if (tid < s) red[tid] = fmaxf(red[tid], red[tid + s]);
        __syncthreads();
    }
    if (tid == 0) g_scale[L] = fmaxf(red[0], 1e-8f);
}

// ----------------------------------------------------------------------------
// Wide repack for int layers 2..10 (grid-strided)
// ----------------------------------------------------------------------------
__global__ void repack_all(const float* w1, const float* w2,
                           const float* w3, const float* w4, const float* w5,
                           const float* w6, const float* w7, const float* w8,
                           const float* w9) {
    const float* ws[9] = {w1,w2,w3,w4,w5,w6,w7,w8,w9};
    const int    ns[9] = {576,1152,4608,16128,52416,194688,11648,52416,28080};
    const int  cins[9] = {8,8,16,32,56,104,208,56,104};
    const int   kks[9] = {9,9,9,9,9,9,1,9,9};
    int8_t* wqs[9] = {g_w2q, g_w3q, g_w4q, g_w5q, g_w6q,
                      g_w7q, g_w8q, g_w9q, g_w10q};

    int gid = blockIdx.x * blockDim.x + threadIdx.x;
    int L = 0, off = gid;
    while (L < 9 && off >= ns[L]) { off -= ns[L]; L++; }
    if (L >= 9) return;

    float s = g_scale[L + 1];
    const float* w = ws[L];
    int cin = cins[L], kk = kks[L];
    int co = off / (cin * kk);
    int rem = off % (cin * kk);
    int ci = rem / kk;
    int t  = rem % kk;
    float v = w[off] / s;
    int q = (int)rintf(fminf(fmaxf(v, -1.f), 1.f));
    wqs[L][(co * kk + t) * cin + ci] = (int8_t)q;
}

// ----------------------------------------------------------------------------
// conv1 sign lists: BYTE offsets into a 3ch x 10row x 34col float tile.
// ----------------------------------------------------------------------------
__global__ void prep_c1(const float* __restrict__ w) {
    int co = threadIdx.x;
    if (co >= 8) return;
    float s = g_scale[0];
    int pc = 0, mc = 0;
    for (int ci = 0; ci < 3; ci++)
        for (int ky = 0; ky < 3; ky++)
            for (int kx = 0; kx < 3; kx++) {
                float v = w[((co * 3 + ci) * 3 + ky) * 3 + kx] / s;
                int q = (int)rintf(fminf(fmaxf(v, -1.f), 1.f));
                unsigned short off = (unsigned short)((ci * 340 + ky * 34 + kx) * 4);
                if (q > 0) g_c1p[co * 32 + pc++] = off;
                else if (q < 0) g_c1m[co * 32 + mc++] = off;
            }
    g_c1cnt[co] = pc;
    g_c1cnt[8 + co] = mc;
}

// ----------------------------------------------------------------------------
// conv1 sparse (round-6 form): s * sum(+/- x) FADD gathers over float tile.
// 256 thr: warp -> cout-pair (warp&3) + pixel-half (warp>>2); lane -> px.
// Lists come from __constant__ (LDC, warp-uniform).
// ----------------------------------------------------------------------------
__global__ __launch_bounds__(256) void conv1_sp(const float* __restrict__ x,
                                                uint32_t* __restrict__ out) {
    __shared__ float s_x[1020];   // 3ch x 10rows x 34cols

    const int t = threadIdx.x;
    const int n = blockIdx.z;
    const int px0 = blockIdx.x * 16, py0 = blockIdx.y * 4;

    for (int i = t; i < 1020; i += 256) {
        int ch = i / 340, rem = i % 340, r = rem / 34, c = rem % 34;
        int gy = 2 * py0 - 1 + r;
        int gx = 2 * px0 - 1 + c;
        float v = 0.f;
        if ((unsigned)gx < 640u && (unsigned)gy < 640u)
            v = __ldg(x + ((size_t)(n * 3 + ch) * 640 + gy) * 640 + gx);
        s_x[i] = v;
    }
    __syncthreads();

    const int warp = t >> 5, lane = t & 31;
    const int pair = warp & 3, half = warp >> 2;
    const int pid = half * 32 + lane;
    const int tx = pid & 15, ty = pid >> 4;
    const char* sb = (const char*)s_x + ((2 * ty) * 34 + 2 * tx) * 4;

    float s = g_scale[0];
    uint32_t codes[2];
#pragma unroll
    for (int cc = 0; cc < 2; cc++) {
        int co = pair * 2 + cc;
        float a0 = 0.f, a1 = 0.f, a2 = 0.f, a3 = 0.f;
        int pcnt = c_c1cnt[co], mcnt = c_c1cnt[8 + co];
        for (int i = 0; i < pcnt; i++) {
            const float* p = (const float*)(sb + c_c1p[co * 32 + i]);
            a0 += p[0];  a1 += p[1];
            a2 += p[34]; a3 += p[35];
        }
        for (int i = 0; i < mcnt; i++) {
            const float* p = (const float*)(sb + c_c1m[co * 32 + i]);
            a0 -= p[0];  a1 -= p[1];
            a2 -= p[34]; a3 -= p[35];
        }
        float mx = fmaxf(fmaxf(a0, a1), fmaxf(a2, a3));
        codes[cc] = (uint32_t)(int)rintf(fminf(fmaxf(s * mx * 0.5f, 0.f), 3.f));
    }

    uint32_t v16 = codes[0] | (codes[1] << 8);
    size_t widx = ((size_t)n * 2 + (pair >> 1)) * 102400
                + (size_t)(py0 + ty) * 320 + (px0 + tx);
    *(uint16_t*)((uint8_t*)out + widx * 4 + (pair & 1) * 2) = (uint16_t)v16;
}

// ----------------------------------------------------------------------------
// Int conv 3x3 + quant_relu + 2x2 pool (round-4 dense). 4 conv cols x 4 couts.
// ----------------------------------------------------------------------------
template <int CIN>
__global__ __launch_bounds__(128) void convpool2(const uint32_t* __restrict__ in,
                                                 const int8_t* __restrict__ wq,
                                                 int sidx, uint32_t* __restrict__ out,
                                                 int S, int outW4) {
    constexpr int W4 = CIN / 4;
    __shared__ int ws[4 * 9 * W4];
    const int* wg = (const int*)wq + blockIdx.z * (4 * 9 * W4);
    for (int i = threadIdx.x; i < 4 * 9 * W4; i += 128) ws[i] = wg[i];
    __syncthreads();

    const int P = S >> 1, Ph = P >> 1, HW = S * S;
    int p = blockIdx.x * 128 + threadIdx.x;
    if (p >= P * Ph) return;
    int py = p / Ph, pxp = p % Ph;
    int n = blockIdx.y;

    int acc[2][4][4] = {};
    const uint32_t* base = in + (size_t)n * W4 * HW;

#pragma unroll
    for (int r = 0; r < 4; r++) {
        int y = 2 * py + r - 1;
        if ((unsigned)y >= (unsigned)S) continue;
#pragma unroll
        for (int k = 0; k < W4; k++) {
            const uint32_t* rp = base + k * HW + y * S;
            int a[6];
#pragma unroll
            for (int c = 0; c < 6; c++) {
                int xx = 4 * pxp - 1 + c;
                a[c] = ((unsigned)xx < (unsigned)S) ? (int)__ldg(rp + xx) : 0;
            }
#pragma unroll
            for (int ky = 0; ky < 3; ky++) {
                int dy = r - ky;
                if (dy < 0 || dy > 1) continue;
#pragma unroll
                for (int kx = 0; kx < 3; kx++) {
#pragma unroll
                    for (int co = 0; co < 4; co++) {
                        int w = ws[(co * 9 + ky * 3 + kx) * W4 + k];
#pragma unroll
                        for (int j = 0; j < 4; j++)
                            acc[dy][j][co] = __dp4a(a[j + kx], w, acc[dy][j][co]);
                    }
                }
            }
        }
    }

    float s = g_scale[sidx];
    uint32_t w0 = 0, w1 = 0;
#pragma unroll
    for (int co = 0; co < 4; co++) {
        int m0 = max(max(acc[0][0][co], acc[0][1][co]),
                     max(acc[1][0][co], acc[1][1][co]));
        int m1 = max(max(acc[0][2][co], acc[0][3][co]),
                     max(acc[1][2][co], acc[1][3][co]));
        w0 |= ((uint32_t)(int)rintf(fminf(fmaxf(s * (float)m0, 0.f), 3.f))) << (co * 8);
        w1 |= ((uint32_t)(int)rintf(fminf(fmaxf(s * (float)m1, 0.f), 3.f))) << (co * 8);
    }
    uint32_t* op = out + ((size_t)n * outW4 + blockIdx.z) * (P * P) + py * P + 2 * pxp;
    op[0] = w0;
    op[1] = w1;
}

// ----------------------------------------------------------------------------
// Int conv 3x3 on 20x20 (round-4 dense). 4 columns x NCO couts.
// ----------------------------------------------------------------------------
template <int CIN, int NCO>
__global__ __launch_bounds__(128) void conv3s(const uint32_t* __restrict__ in,
                                              const int8_t* __restrict__ wq,
                                              int sidx, uint32_t* __restrict__ out,
                                              int outW4) {
    constexpr int W4 = CIN / 4;
    __shared__ int ws[NCO * 9 * W4];
    const int* wg = (const int*)wq + blockIdx.z * (NCO * 9 * W4);
    for (int i = threadIdx.x; i < NCO * 9 * W4; i += 128) ws[i] = wg[i];
    __syncthreads();

    int t = threadIdx.x;
    if (t >= 100) return;
    int py = t / 5, px0 = (t % 5) * 4;
    int n = blockIdx.y;

    int acc[4][NCO];
#pragma unroll
    for (int j = 0; j < 4; j++)
#pragma unroll
        for (int co = 0; co < NCO; co++) acc[j][co] = 0;

    const uint32_t* base = in + (size_t)n * W4 * 400;

#pragma unroll
    for (int ky = 0; ky < 3; ky++) {
        int y = py + ky - 1;
        if ((unsigned)y >= 20u) continue;
        for (int k = 0; k < W4; k++) {
            const uint32_t* rp = base + k * 400 + y * 20;
            int a[6];
#pragma unroll
            for (int c = 0; c < 6; c++) {
                int xx = px0 - 1 + c;
                a[c] = ((unsigned)xx < 20u) ? (int)__ldg(rp + xx) : 0;
            }
#pragma unroll
            for (int kx = 0; kx < 3; kx++) {
#pragma unroll
                for (int co = 0; co < NCO; co++) {
                    int w = ws[(co * 9 + ky * 3 + kx) * W4 + k];
#pragma unroll
                    for (int j = 0; j < 4; j++)
                        acc[j][co] = __dp4a(a[j + kx], w, acc[j][co]);
                }
            }
        }
    }

    float s = g_scale[sidx];
#pragma unroll
    for (int wg4 = 0; wg4 < NCO / 4; wg4++) {
        uint32_t v[4];
#pragma unroll
        for (int j = 0; j < 4; j++) {
            uint32_t b = 0;
#pragma unroll
            for (int co = 0; co < 4; co++) {
                int cc = wg4 * 4 + co;
                b |= ((uint32_t)(int)rintf(fminf(fmaxf(s * (float)acc[j][cc], 0.f), 3.f)))
                     << (co * 8);
            }
            v[j] = b;
        }
        int plane = blockIdx.z * (NCO / 4) + wg4;
        *(uint4*)(out + ((size_t)n * outW4 + plane) * 400 + py * 20 + px0) =
            make_uint4(v[0], v[1], v[2], v[3]);
    }
}

// ----------------------------------------------------------------------------
// Int conv 1x1 on 20x20 (round-4 dense). 4 pixels x NCO couts.
// ----------------------------------------------------------------------------
template <int CIN, int NCO>
__global__ __launch_bounds__(128) void conv1x1s(const uint32_t* __restrict__ in,
                                                const int8_t* __restrict__ wq,
                                                int sidx, uint32_t* __restrict__ out,
                                                int outW4) {
    constexpr int W4 = CIN / 4;
    __shared__ int ws[NCO * W4];
    const int* wg = (const int*)wq + blockIdx.z * (NCO * W4);
    for (int i = threadIdx.x; i < NCO * W4; i += 128) ws[i] = wg[i];
    __syncthreads();

    int t = threadIdx.x;
    if (t >= 100) return;
    int p0 = t * 4;
    int n = blockIdx.y;

    int acc[4][NCO];
#pragma unroll
    for (int j = 0; j < 4; j++)
#pragma unroll
        for (int co = 0; co < NCO; co++) acc[j][co] = 0;

    const uint32_t* base = in + (size_t)n * W4 * 400;
#pragma unroll
    for (int k = 0; k < W4; k++) {
        uint4 av = __ldg((const uint4*)(base + k * 400 + p0));
        int a[4] = {(int)av.x, (int)av.y, (int)av.z, (int)av.w};
#pragma unroll
        for (int co = 0; co < NCO; co++) {
            int w = ws[co * W4 + k];
#pragma unroll
            for (int j = 0; j < 4; j++)
                acc[j][co] = __dp4a(a[j], w, acc[j][co]);
        }
    }

    float s = g_scale[sidx];
#pragma unroll
    for (int wg4 = 0; wg4 < NCO / 4; wg4++) {
        uint32_t v[4];
#pragma unroll
        for (int j = 0; j < 4; j++) {
            uint32_t b = 0;
#pragma unroll
            for (int co = 0; co < 4; co++) {
                int cc = wg4 * 4 + co;
                b |= ((uint32_t)(int)rintf(fminf(fmaxf(s * (float)acc[j][cc], 0.f), 3.f)))
                     << (co * 8);
            }
            v[j] = b;
        }
        int plane = blockIdx.z * (NCO / 4) + wg4;
        *(uint4*)(out + ((size_t)n * outW4 + plane) * 400 + p0) =
            make_uint4(v[0], v[1], v[2], v[3]);
    }
}

// ----------------------------------------------------------------------------
// Layer 10 (round-4 dense): 3x3 104->30 + quant_hardtanh, fp32 NCHW out.
// ----------------------------------------------------------------------------
__global__ __launch_bounds__(128) void conv10_out(const uint32_t* __restrict__ in,
                                                  const int8_t* __restrict__ wq,
                                                  float* __restrict__ out) {
    constexpr int W4 = 26;
    __shared__ int ws[3 * 9 * W4];
    const int* wg = (const int*)wq + blockIdx.z * (3 * 9 * W4);
    for (int i = threadIdx.x; i < 3 * 9 * W4; i += 128) ws[i] = wg[i];
    __syncthreads();

    int t = threadIdx.x;
    if (t >= 100) return;
    int py = t / 5, px0 = (t % 5) * 4;
    int n = blockIdx.y;

    int acc[4][3];
#pragma unroll
    for (int j = 0; j < 4; j++)
#pragma unroll
        for (int co = 0; co < 3; co++) acc[j][co] = 0;

    const uint32_t* base = in + (size_t)n * W4 * 400;
#pragma unroll
    for (int ky = 0; ky < 3; ky++) {
        int y = py + ky - 1;
        if ((unsigned)y >= 20u) continue;
        for (int k = 0; k < W4; k++) {
            const uint32_t* rp = base + k * 400 + y * 20;
            int a[6];
#pragma unroll
            for (int c = 0; c < 6; c++) {
                int xx = px0 - 1 + c;
                a[c] = ((unsigned)xx < 20u) ? (int)__ldg(rp + xx) : 0;
            }
#pragma unroll
            for (int kx = 0; kx < 3; kx++) {
#pragma unroll
                for (int co = 0; co < 3; co++) {
                    int w = ws[(co * 9 + ky * 3 + kx) * W4 + k];
#pragma unroll
                    for (int j = 0; j < 4; j++)
                        acc[j][co] = __dp4a(a[j + kx], w, acc[j][co]);
                }
            }
        }
    }

    float s = g_scale[9];
#pragma unroll
    for (int co = 0; co < 3; co++) {
        float4 v;
        float* vp = (float*)&v;
#pragma unroll
        for (int j = 0; j < 4; j++) {
            float x = 2.f * s * (float)acc[j][co];
            float tt = fminf(fmaxf(x, 0.f), 1.f);
            vp[j] = rintf(tt * 255.f) * (1.f / 255.f);
        }
        int cg = blockIdx.z * 3 + co;
        *(float4*)(out + ((size_t)(n * 30 + cg)) * 400 + py * 20 + px0) = v;
    }
}

// ----------------------------------------------------------------------------
// Launch
// ----------------------------------------------------------------------------
extern "C" void kernel_launch(void* const* d_in, const int* in_sizes, int n_in,
                              void* d_out, int out_size) {
    const float* x = (const float*)d_in[0];
    const float* w[10];
    for (int i = 0; i < 10; i++) w[i] = (const float*)d_in[1 + i];

    void *p_w2, *p_w3, *p_w4, *p_w5, *p_w6, *p_w7, *p_w8, *p_w9, *p_w10;
    void *p_a1, *p_a2, *p_a3, *p_a4, *p_a5, *p_a6, *p_a7, *p_a8, *p_a9;
    void *p_c1p, *p_c1m, *p_c1cnt;
    cudaGetSymbolAddress(&p_w2, g_w2q);
    cudaGetSymbolAddress(&p_w3, g_w3q);
    cudaGetSymbolAddress(&p_w4, g_w4q);
    cudaGetSymbolAddress(&p_w5, g_w5q);
    cudaGetSymbolAddress(&p_w6, g_w6q);
    cudaGetSymbolAddress(&p_w7, g_w7q);
    cudaGetSymbolAddress(&p_w8, g_w8q);
    cudaGetSymbolAddress(&p_w9, g_w9q);
    cudaGetSymbolAddress(&p_w10, g_w10q);
    cudaGetSymbolAddress(&p_a1, g_act1);
    cudaGetSymbolAddress(&p_a2, g_act2);
    cudaGetSymbolAddress(&p_a3, g_act3);
    cudaGetSymbolAddress(&p_a4, g_act4);
    cudaGetSymbolAddress(&p_a5, g_act5);
    cudaGetSymbolAddress(&p_a6, g_act6);
    cudaGetSymbolAddress(&p_a7, g_act7);
    cudaGetSymbolAddress(&p_a8, g_act8);
    cudaGetSymbolAddress(&p_a9, g_act9);
    cudaGetSymbolAddress(&p_c1p, g_c1p);
    cudaGetSymbolAddress(&p_c1m, g_c1m);
    cudaGetSymbolAddress(&p_c1cnt, g_c1cnt);

    const uint32_t *a1 = (const uint32_t*)p_a1, *a2 = (const uint32_t*)p_a2,
                   *a3 = (const uint32_t*)p_a3, *a4 = (const uint32_t*)p_a4,
                   *a5 = (const uint32_t*)p_a5, *a6 = (const uint32_t*)p_a6,
                   *a7 = (const uint32_t*)p_a7, *a8 = (const uint32_t*)p_a8,
                   *a9 = (const uint32_t*)p_a9;

    absmax10<<<10, 256>>>(w[0], w[1], w[2], w[3], w[4], w[5], w[6], w[7], w[8], w[9]);
    repack_all<<<1414, 256>>>(w[1], w[2], w[3], w[4], w[5], w[6], w[7], w[8], w[9]);
    prep_c1<<<1, 32>>>(w[0]);

    // stage -> __constant__ (device-to-device async; graph-capturable)
    cudaMemcpyToSymbolAsync(c_c1p, p_c1p, 8 * 32 * sizeof(unsigned short), 0,
                            cudaMemcpyDeviceToDevice, 0);
    cudaMemcpyToSymbolAsync(c_c1m, p_c1m, 8 * 32 * sizeof(unsigned short), 0,
                            cudaMemcpyDeviceToDevice, 0);
    cudaMemcpyToSymbolAsync(c_c1cnt, p_c1cnt, 16 * sizeof(int), 0,
                            cudaMemcpyDeviceToDevice, 0);

    conv1_sp<<<dim3(20, 80, 16), 256>>>(x, (uint32_t*)p_a1);

    convpool2<8><<<dim3(100, 16, 2), 128>>>(a1, (const int8_t*)p_w2, 1,
                                            (uint32_t*)p_a2, 320, 2);
    convpool2<8><<<dim3(25, 16, 4), 128>>>(a2, (const int8_t*)p_w3, 2,
                                           (uint32_t*)p_a3, 160, 4);
    convpool2<16><<<dim3(7, 16, 8), 128>>>(a3, (const int8_t*)p_w4, 3,
                                           (uint32_t*)p_a4, 80, 8);
    convpool2<32><<<dim3(2, 16, 14), 128>>>(a4, (const int8_t*)p_w5, 4,
                                            (uint32_t*)p_a5, 40, 14);
    conv3s<56, 4><<<dim3(1, 16, 26), 128>>>(a5, (const int8_t*)p_w6, 5,
                                            (uint32_t*)p_a6, 26);
    conv3s<104, 4><<<dim3(1, 16, 52), 128>>>(a6, (const int8_t*)p_w7, 6,
                                             (uint32_t*)p_a7, 52);
    conv1x1s<208, 4><<<dim3(1, 16, 14), 128>>>(a7, (const int8_t*)p_w8, 7,
                                               (uint32_t*)p_a8, 14);
    conv3s<56, 4><<<dim3(1, 16, 26), 128>>>(a8, (const int8_t*)p_w9, 8,
                                            (uint32_t*)p_a9, 26);
    conv10_out<<<dim3(1, 16, 10), 128>>>(a9, (const int8_t*)p_w10, (float*)d_out);
}